// round 2
// baseline (speedup 1.0000x reference)
#include <cuda_runtime.h>
#include <cstdint>

// ---------------------------------------------------------------------------
// R2: batch-paired f32x2 accumulators, k-major activations (natural float2
// pairs, no duplication), pre-duplicated weights ({w,w} float2 built once by a
// prep kernel) so the inner loop is pure LDS + FFMA2 with zero packing MOVs.
// Warp tile 32 cols x 32 batch; lane = 8 pairGroups x 4 colGroups;
// thread = 2 pairs x 8 cols = 16 f32x2 acc. Weights stream via 3-deep
// cp.async ring of 16-row dup tiles.
// ---------------------------------------------------------------------------

typedef unsigned long long ull;

#define THREADS 256
#define TILE_B  32
#define KTROWS  16

__device__ __forceinline__ void fma2(ull& acc, ull a, ull b) {
    asm("fma.rn.f32x2 %0, %1, %2, %0;" : "+l"(acc) : "l"(a), "l"(b));
}
__device__ __forceinline__ void unpack2(ull v, float& lo, float& hi) {
    asm("mov.b64 {%0,%1}, %2;" : "=f"(lo), "=f"(hi) : "l"(v));
}
__device__ __forceinline__ void cp16(uint32_t dst, const void* src) {
    asm volatile("cp.async.cg.shared.global [%0], [%1], 16;" :: "r"(dst), "l"(src));
}

// duplicated weights, built once per graph replay by dup_weights_kernel
__device__ __align__(16) float2 g_w1d[13 * 256];
__device__ __align__(16) float2 g_w2d[256 * 256];
__device__ __align__(16) float2 g_w3d[256 * 256];

__global__ void dup_weights_kernel(const float* __restrict__ w1,
                                   const float* __restrict__ w2,
                                   const float* __restrict__ w3) {
    int i = blockIdx.x * blockDim.x + threadIdx.x;
    if (i < 13 * 256) g_w1d[i] = make_float2(w1[i], w1[i]);
    if (i < 256 * 256) {
        g_w2d[i] = make_float2(w2[i], w2[i]);
        g_w3d[i] = make_float2(w3[i], w3[i]);
    }
}

// SMEM float offsets
#define OFF_WBUF 0        // 3 * 16*512 = 24576   (3 dup weight tiles, 32KB ea)
#define OFF_W1S  24576    // 13*512 = 6656        (dup W1, resident)
#define OFF_ACTA 31232    // 256*32 = 8192        (k-major act, float pairs)
#define OFF_ACTB 39424    // 8192
#define OFF_B1D  47616    // 512 (dup bias)
#define OFF_B2D  48128    // 512
#define OFF_B3D  48640    // 512
#define OFF_WMU  49152    // 512
#define OFF_BMU  49664    // 2 (+6 pad)
#define OFF_OBS  49672    // 13*32 = 416 (k-major obs)
#define OFF_AS   50088    // 64
#define SMEM_FLOATS 50152
#define SMEM_BYTES  (SMEM_FLOATS * 4)   // 200,608 B

// prefetch one 16-row dup weight tile (32KB) into smem buffer
__device__ __forceinline__ void pf_tile(uint32_t wbase, const float2* __restrict__ Wg,
                                        int t, int tx) {
    const float4* src = (const float4*)(Wg + t * KTROWS * 256) + tx;  // 2048 float4 / tile
    uint32_t dst = wbase + tx * 16;
    #pragma unroll
    for (int r = 0; r < 8; r++) cp16(dst + r * 4096, src + r * 256);
    asm volatile("cp.async.commit_group;");
}

__device__ __forceinline__ void bias_init(ull acc[2][4][2], const float* biasD,
                                          int w, int cg) {
    #pragma unroll
    for (int i = 0; i < 4; i++) {
        ulonglong2 bv = *(const ulonglong2*)(biasD + w * 64 + i * 16 + cg * 4);
        acc[0][i][0] = bv.x; acc[0][i][1] = bv.y;
        acc[1][i][0] = bv.x; acc[1][i][1] = bv.y;
    }
}

__device__ __forceinline__ void epilogue_relu(ull acc[2][4][2], float* actOut,
                                              int w, int cg, int gg) {
    #pragma unroll
    for (int p = 0; p < 2; p++)
        #pragma unroll
        for (int i = 0; i < 4; i++)
            #pragma unroll
            for (int u = 0; u < 2; u++) {
                float lo, hi; unpack2(acc[p][i][u], lo, hi);
                lo = fmaxf(lo, 0.f); hi = fmaxf(hi, 0.f);
                int j = w * 32 + i * 8 + cg * 2 + u;
                *(float2*)(actOut + j * 32 + gg * 4 + p * 2) = make_float2(lo, hi);
            }
}

// input layer: obs(13) -> 256, W1 dup resident in smem
__device__ __forceinline__ void layer_in(const float* __restrict__ obsT,
                                         float* __restrict__ actOut,
                                         const float* __restrict__ W1s,
                                         const float* __restrict__ biasD, int tx) {
    const int w = tx >> 5, cg = tx & 3, gg = (tx & 31) >> 2;
    ull acc[2][4][2];
    bias_init(acc, biasD, w, cg);
    #pragma unroll
    for (int k = 0; k < 13; k++) {
        ull a0 = *(const ull*)(obsT + k * 32 + gg * 4);
        ull a1 = *(const ull*)(obsT + k * 32 + gg * 4 + 2);
        #pragma unroll
        for (int i = 0; i < 4; i++) {
            ulonglong2 wv = *(const ulonglong2*)(W1s + k * 512 + w * 64 + i * 16 + cg * 4);
            fma2(acc[0][i][0], a0, wv.x);
            fma2(acc[0][i][1], a0, wv.y);
            fma2(acc[1][i][0], a1, wv.x);
            fma2(acc[1][i][1], a1, wv.y);
        }
    }
    epilogue_relu(acc, actOut, w, cg, gg);
    __syncthreads();
}

// 256 -> 256 layer, weights streamed through a 3-buffer cp.async ring
__device__ __forceinline__ void layer_mid(const float* __restrict__ actIn,
                                          float* __restrict__ actOut,
                                          const float2* __restrict__ Wg,
                                          const float* __restrict__ biasD,
                                          const float* __restrict__ Wbuf,
                                          uint32_t wbufs, int tx, bool pre) {
    const int w = tx >> 5, cg = tx & 3, gg = (tx & 31) >> 2;
    ull acc[2][4][2];
    bias_init(acc, biasD, w, cg);

    if (!pre) {
        pf_tile(wbufs, Wg, 0, tx);
        pf_tile(wbufs + 32768u, Wg, 1, tx);
    }

    #pragma unroll 1
    for (int kt = 0; kt < 16; kt++) {
        if (kt < 15) asm volatile("cp.async.wait_group 1;");
        else         asm volatile("cp.async.wait_group 0;");
        __syncthreads();
        if (kt < 14) pf_tile(wbufs + (uint32_t)((kt + 2) % 3) * 32768u, Wg, kt + 2, tx);

        const float* WT = Wbuf + (kt % 3) * 8192;
        const float* aT = actIn + kt * 512;
        #pragma unroll 4
        for (int kk = 0; kk < 16; kk++) {
            ull a0 = *(const ull*)(aT + kk * 32 + gg * 4);
            ull a1 = *(const ull*)(aT + kk * 32 + gg * 4 + 2);
            #pragma unroll
            for (int i = 0; i < 4; i++) {
                ulonglong2 wv = *(const ulonglong2*)(WT + kk * 512 + w * 64 + i * 16 + cg * 4);
                fma2(acc[0][i][0], a0, wv.x);
                fma2(acc[0][i][1], a0, wv.y);
                fma2(acc[1][i][0], a1, wv.x);
                fma2(acc[1][i][1], a1, wv.y);
            }
        }
    }
    __syncthreads();  // all reads of Wbuf/actIn done before epilogue overwrite patterns
    epilogue_relu(acc, actOut, w, cg, gg);
    __syncthreads();
}

__device__ __forceinline__ void write_obs_T(float* obsT, int b, float px, float py) {
    const float iw = 0.1f;
    obsT[0 * 32 + b] = px * iw;
    obsT[1 * 32 + b] = py * iw;
    obsT[2 * 32 + b] = (4.0f - px) * iw;
    obsT[3 * 32 + b] = (3.0f - py) * iw;
    const float ox[3]  = {1.75f, 1.75f, 3.75f};
    const float oy[3]  = {1.75f, 3.75f, 2.00f};
    const float orr[3] = {0.38f, 0.42f, 0.34f};
    #pragma unroll
    for (int i = 0; i < 3; i++) {
        float dx = px - ox[i], dy = py - oy[i];
        float dist = sqrtf(dx * dx + dy * dy + 1e-9f);
        obsT[(4 + 2 * i) * 32 + b] = -dx * iw;
        obsT[(5 + 2 * i) * 32 + b] = -dy * iw;
        obsT[(10 + i) * 32 + b]    = dist - orr[i];
    }
}

__global__ void __launch_bounds__(THREADS, 1)
rollout_kernel(const float* __restrict__ pos0, const float* __restrict__ wind,
               const float* __restrict__ b1g, const float* __restrict__ b2g,
               const float* __restrict__ b3g, const float* __restrict__ wmu,
               const float* __restrict__ bmug, float* __restrict__ out)
{
    extern __shared__ float sm[];
    float* Wbuf = sm + OFF_WBUF;
    float* W1s  = sm + OFF_W1S;
    float* actA = sm + OFF_ACTA;
    float* actB = sm + OFF_ACTB;
    float* b1d  = sm + OFF_B1D;
    float* b2d  = sm + OFF_B2D;
    float* b3d  = sm + OFF_B3D;
    float* wmuS = sm + OFF_WMU;
    float* bmuS = sm + OFF_BMU;
    float* obsT = sm + OFF_OBS;
    float* aS   = sm + OFF_AS;

    const int tx = threadIdx.x;
    const int b0 = blockIdx.x * TILE_B;
    const uint32_t wbufs = (uint32_t)__cvta_generic_to_shared(Wbuf);

    // stage resident dup W1, dup biases, head weights
    for (int i = tx; i < 3328; i += THREADS) ((float2*)W1s)[i] = g_w1d[i];
    {
        float v;
        v = b1g[tx]; ((float2*)b1d)[tx] = make_float2(v, v);
        v = b2g[tx]; ((float2*)b2d)[tx] = make_float2(v, v);
        v = b3g[tx]; ((float2*)b3d)[tx] = make_float2(v, v);
    }
    for (int i = tx; i < 512; i += THREADS) wmuS[i] = wmu[i];
    if (tx < 2) bmuS[tx] = bmug[tx];

    // per-lane rollout state
    float px = 0.f, py = 0.f, wx = 0.f, wy = 0.f;
    float m_s = -1e30f, s_s = 0.f, m_r = -1e30f, s_r = 0.f;
    if (tx < TILE_B) {
        px = pos0[(b0 + tx) * 2 + 0]; py = pos0[(b0 + tx) * 2 + 1];
        wx = wind[(b0 + tx) * 2 + 0]; wy = wind[(b0 + tx) * 2 + 1];
        write_obs_T(obsT, tx, px, py);
    }
    __syncthreads();

    #pragma unroll 1
    for (int t = 0; t < 64; t++) {
        // start streaming layer-2 weights while layer 1 computes
        pf_tile(wbufs, g_w2d, 0, tx);
        pf_tile(wbufs + 32768u, g_w2d, 1, tx);

        layer_in(obsT, actA, W1s, b1d, tx);
        layer_mid(actA, actB, g_w2d, b2d, Wbuf, wbufs, tx, true);
        layer_mid(actB, actA, g_w3d, b3d, Wbuf, wbufs, tx, false);

        // output head: a = clip(h3 @ wmu + bmu); h3 is k-major in actA
        if (tx < 64) {
            int m = tx & 1, b = tx >> 1;
            float a0 = bmuS[m], a1 = 0.f, a2 = 0.f, a3 = 0.f;
            #pragma unroll 8
            for (int j = 0; j < 256; j += 4) {
                a0 = fmaf(actA[(j + 0) * 32 + b], wmuS[(j + 0) * 2 + m], a0);
                a1 = fmaf(actA[(j + 1) * 32 + b], wmuS[(j + 1) * 2 + m], a1);
                a2 = fmaf(actA[(j + 2) * 32 + b], wmuS[(j + 2) * 2 + m], a2);
                a3 = fmaf(actA[(j + 3) * 32 + b], wmuS[(j + 3) * 2 + m], a3);
            }
            float acc = (a0 + a1) + (a2 + a3);
            aS[b * 2 + m] = fminf(fmaxf(acc, -1.f), 1.f);
        }
        __syncthreads();

        // dynamics + online STREL accumulators + next obs
        if (tx < TILE_B) {
            float vx = 2.f * aS[tx * 2 + 0] + wx;
            float vy = 2.f * aS[tx * 2 + 1] + wy;
            #pragma unroll
            for (int s = 0; s < 4; s++) {
                px = fminf(fmaxf(px + 0.0625f * vx, -4.f), 10.f);
                py = fminf(fmaxf(py + 0.0625f * vy, -4.f), 10.f);
            }
            float dx = px - 1.75f, dy = py - 1.75f;
            float x0 = -50.f * (sqrtf(dx * dx + dy * dy + 1e-9f) - 0.38f);
            dx = px - 1.75f; dy = py - 3.75f;
            float x1 = -50.f * (sqrtf(dx * dx + dy * dy + 1e-9f) - 0.42f);
            dx = px - 3.75f; dy = py - 2.00f;
            float x2 = -50.f * (sqrtf(dx * dx + dy * dy + 1e-9f) - 0.34f);
            float mm = fmaxf(x0, fmaxf(x1, x2));
            float safe = -(mm + logf(expf(x0 - mm) + expf(x1 - mm) + expf(x2 - mm))) * 0.02f;

            float dgx = px - 4.f, dgy = py - 3.f;
            float reach = 0.45f - sqrtf(dgx * dgx + dgy * dgy + 1e-9f);

            float xs = -8.f * safe;
            if (xs > m_s) { s_s = s_s * expf(m_s - xs) + 1.f; m_s = xs; }
            else          { s_s += expf(xs - m_s); }
            float xr = 8.f * reach;
            if (xr > m_r) { s_r = s_r * expf(m_r - xr) + 1.f; m_r = xr; }
            else          { s_r += expf(xr - m_r); }

            write_obs_T(obsT, tx, px, py);
        }
        __syncthreads();
    }

    if (tx < TILE_B) {
        float rho_safe  = -(m_s + logf(s_s)) * 0.125f;
        float rho_reach =  (m_r + logf(s_r)) * 0.125f;
        float u0 = -8.f * rho_safe, u1 = -8.f * rho_reach;
        float mm = fmaxf(u0, u1);
        float rho = -(mm + logf(expf(u0 - mm) + expf(u1 - mm))) * 0.125f;
        out[b0 + tx] = rho;
    }
}

extern "C" void kernel_launch(void* const* d_in, const int* in_sizes, int n_in,
                              void* d_out, int out_size) {
    const float* pos0 = (const float*)d_in[0];
    const float* wind = (const float*)d_in[1];
    const float* w1   = (const float*)d_in[2];
    const float* b1   = (const float*)d_in[3];
    const float* w2   = (const float*)d_in[4];
    const float* b2   = (const float*)d_in[5];
    const float* w3   = (const float*)d_in[6];
    const float* b3   = (const float*)d_in[7];
    const float* wmu  = (const float*)d_in[8];
    const float* bmu  = (const float*)d_in[9];
    float* out = (float*)d_out;

    dup_weights_kernel<<<256, 256>>>(w1, w2, w3);

    cudaFuncSetAttribute(rollout_kernel,
                         cudaFuncAttributeMaxDynamicSharedMemorySize, SMEM_BYTES);
    int grid = out_size / TILE_B;  // 1024
    rollout_kernel<<<grid, THREADS, SMEM_BYTES>>>(pos0, wind, b1, b2, b3,
                                                  wmu, bmu, out);
}

// round 3
// speedup vs baseline: 1.0006x; 1.0006x over previous
#include <cuda_runtime.h>
#include <cstdint>

// ---------------------------------------------------------------------------
// R2: batch-paired f32x2 accumulators, k-major activations (natural float2
// pairs, no duplication), pre-duplicated weights ({w,w} float2 built once by a
// prep kernel) so the inner loop is pure LDS + FFMA2 with zero packing MOVs.
// Warp tile 32 cols x 32 batch; lane = 8 pairGroups x 4 colGroups;
// thread = 2 pairs x 8 cols = 16 f32x2 acc. Weights stream via 3-deep
// cp.async ring of 16-row dup tiles.
// ---------------------------------------------------------------------------

typedef unsigned long long ull;

#define THREADS 256
#define TILE_B  32
#define KTROWS  16

__device__ __forceinline__ void fma2(ull& acc, ull a, ull b) {
    asm("fma.rn.f32x2 %0, %1, %2, %0;" : "+l"(acc) : "l"(a), "l"(b));
}
__device__ __forceinline__ void unpack2(ull v, float& lo, float& hi) {
    asm("mov.b64 {%0,%1}, %2;" : "=f"(lo), "=f"(hi) : "l"(v));
}
__device__ __forceinline__ void cp16(uint32_t dst, const void* src) {
    asm volatile("cp.async.cg.shared.global [%0], [%1], 16;" :: "r"(dst), "l"(src));
}

// duplicated weights, built once per graph replay by dup_weights_kernel
__device__ __align__(16) float2 g_w1d[13 * 256];
__device__ __align__(16) float2 g_w2d[256 * 256];
__device__ __align__(16) float2 g_w3d[256 * 256];

__global__ void dup_weights_kernel(const float* __restrict__ w1,
                                   const float* __restrict__ w2,
                                   const float* __restrict__ w3) {
    int i = blockIdx.x * blockDim.x + threadIdx.x;
    if (i < 13 * 256) g_w1d[i] = make_float2(w1[i], w1[i]);
    if (i < 256 * 256) {
        g_w2d[i] = make_float2(w2[i], w2[i]);
        g_w3d[i] = make_float2(w3[i], w3[i]);
    }
}

// SMEM float offsets
#define OFF_WBUF 0        // 3 * 16*512 = 24576   (3 dup weight tiles, 32KB ea)
#define OFF_W1S  24576    // 13*512 = 6656        (dup W1, resident)
#define OFF_ACTA 31232    // 256*32 = 8192        (k-major act, float pairs)
#define OFF_ACTB 39424    // 8192
#define OFF_B1D  47616    // 512 (dup bias)
#define OFF_B2D  48128    // 512
#define OFF_B3D  48640    // 512
#define OFF_WMU  49152    // 512
#define OFF_BMU  49664    // 2 (+6 pad)
#define OFF_OBS  49672    // 13*32 = 416 (k-major obs)
#define OFF_AS   50088    // 64
#define SMEM_FLOATS 50152
#define SMEM_BYTES  (SMEM_FLOATS * 4)   // 200,608 B

// prefetch one 16-row dup weight tile (32KB) into smem buffer
__device__ __forceinline__ void pf_tile(uint32_t wbase, const float2* __restrict__ Wg,
                                        int t, int tx) {
    const float4* src = (const float4*)(Wg + t * KTROWS * 256) + tx;  // 2048 float4 / tile
    uint32_t dst = wbase + tx * 16;
    #pragma unroll
    for (int r = 0; r < 8; r++) cp16(dst + r * 4096, src + r * 256);
    asm volatile("cp.async.commit_group;");
}

__device__ __forceinline__ void bias_init(ull acc[2][4][2], const float* biasD,
                                          int w, int cg) {
    #pragma unroll
    for (int i = 0; i < 4; i++) {
        ulonglong2 bv = *(const ulonglong2*)(biasD + w * 64 + i * 16 + cg * 4);
        acc[0][i][0] = bv.x; acc[0][i][1] = bv.y;
        acc[1][i][0] = bv.x; acc[1][i][1] = bv.y;
    }
}

__device__ __forceinline__ void epilogue_relu(ull acc[2][4][2], float* actOut,
                                              int w, int cg, int gg) {
    #pragma unroll
    for (int p = 0; p < 2; p++)
        #pragma unroll
        for (int i = 0; i < 4; i++)
            #pragma unroll
            for (int u = 0; u < 2; u++) {
                float lo, hi; unpack2(acc[p][i][u], lo, hi);
                lo = fmaxf(lo, 0.f); hi = fmaxf(hi, 0.f);
                int j = w * 32 + i * 8 + cg * 2 + u;
                *(float2*)(actOut + j * 32 + gg * 4 + p * 2) = make_float2(lo, hi);
            }
}

// input layer: obs(13) -> 256, W1 dup resident in smem
__device__ __forceinline__ void layer_in(const float* __restrict__ obsT,
                                         float* __restrict__ actOut,
                                         const float* __restrict__ W1s,
                                         const float* __restrict__ biasD, int tx) {
    const int w = tx >> 5, cg = tx & 3, gg = (tx & 31) >> 2;
    ull acc[2][4][2];
    bias_init(acc, biasD, w, cg);
    #pragma unroll
    for (int k = 0; k < 13; k++) {
        ull a0 = *(const ull*)(obsT + k * 32 + gg * 4);
        ull a1 = *(const ull*)(obsT + k * 32 + gg * 4 + 2);
        #pragma unroll
        for (int i = 0; i < 4; i++) {
            ulonglong2 wv = *(const ulonglong2*)(W1s + k * 512 + w * 64 + i * 16 + cg * 4);
            fma2(acc[0][i][0], a0, wv.x);
            fma2(acc[0][i][1], a0, wv.y);
            fma2(acc[1][i][0], a1, wv.x);
            fma2(acc[1][i][1], a1, wv.y);
        }
    }
    epilogue_relu(acc, actOut, w, cg, gg);
    __syncthreads();
}

// 256 -> 256 layer, weights streamed through a 3-buffer cp.async ring
__device__ __forceinline__ void layer_mid(const float* __restrict__ actIn,
                                          float* __restrict__ actOut,
                                          const float2* __restrict__ Wg,
                                          const float* __restrict__ biasD,
                                          const float* __restrict__ Wbuf,
                                          uint32_t wbufs, int tx, bool pre) {
    const int w = tx >> 5, cg = tx & 3, gg = (tx & 31) >> 2;
    ull acc[2][4][2];
    bias_init(acc, biasD, w, cg);

    if (!pre) {
        pf_tile(wbufs, Wg, 0, tx);
        pf_tile(wbufs + 32768u, Wg, 1, tx);
    }

    #pragma unroll 1
    for (int kt = 0; kt < 16; kt++) {
        if (kt < 15) asm volatile("cp.async.wait_group 1;");
        else         asm volatile("cp.async.wait_group 0;");
        __syncthreads();
        if (kt < 14) pf_tile(wbufs + (uint32_t)((kt + 2) % 3) * 32768u, Wg, kt + 2, tx);

        const float* WT = Wbuf + (kt % 3) * 8192;
        const float* aT = actIn + kt * 512;
        #pragma unroll 4
        for (int kk = 0; kk < 16; kk++) {
            ull a0 = *(const ull*)(aT + kk * 32 + gg * 4);
            ull a1 = *(const ull*)(aT + kk * 32 + gg * 4 + 2);
            #pragma unroll
            for (int i = 0; i < 4; i++) {
                ulonglong2 wv = *(const ulonglong2*)(WT + kk * 512 + w * 64 + i * 16 + cg * 4);
                fma2(acc[0][i][0], a0, wv.x);
                fma2(acc[0][i][1], a0, wv.y);
                fma2(acc[1][i][0], a1, wv.x);
                fma2(acc[1][i][1], a1, wv.y);
            }
        }
    }
    __syncthreads();  // all reads of Wbuf/actIn done before epilogue overwrite patterns
    epilogue_relu(acc, actOut, w, cg, gg);
    __syncthreads();
}

__device__ __forceinline__ void write_obs_T(float* obsT, int b, float px, float py) {
    const float iw = 0.1f;
    obsT[0 * 32 + b] = px * iw;
    obsT[1 * 32 + b] = py * iw;
    obsT[2 * 32 + b] = (4.0f - px) * iw;
    obsT[3 * 32 + b] = (3.0f - py) * iw;
    const float ox[3]  = {1.75f, 1.75f, 3.75f};
    const float oy[3]  = {1.75f, 3.75f, 2.00f};
    const float orr[3] = {0.38f, 0.42f, 0.34f};
    #pragma unroll
    for (int i = 0; i < 3; i++) {
        float dx = px - ox[i], dy = py - oy[i];
        float dist = sqrtf(dx * dx + dy * dy + 1e-9f);
        obsT[(4 + 2 * i) * 32 + b] = -dx * iw;
        obsT[(5 + 2 * i) * 32 + b] = -dy * iw;
        obsT[(10 + i) * 32 + b]    = dist - orr[i];
    }
}

__global__ void __launch_bounds__(THREADS, 1)
rollout_kernel(const float* __restrict__ pos0, const float* __restrict__ wind,
               const float* __restrict__ b1g, const float* __restrict__ b2g,
               const float* __restrict__ b3g, const float* __restrict__ wmu,
               const float* __restrict__ bmug, float* __restrict__ out)
{
    extern __shared__ float sm[];
    float* Wbuf = sm + OFF_WBUF;
    float* W1s  = sm + OFF_W1S;
    float* actA = sm + OFF_ACTA;
    float* actB = sm + OFF_ACTB;
    float* b1d  = sm + OFF_B1D;
    float* b2d  = sm + OFF_B2D;
    float* b3d  = sm + OFF_B3D;
    float* wmuS = sm + OFF_WMU;
    float* bmuS = sm + OFF_BMU;
    float* obsT = sm + OFF_OBS;
    float* aS   = sm + OFF_AS;

    const int tx = threadIdx.x;
    const int b0 = blockIdx.x * TILE_B;
    const uint32_t wbufs = (uint32_t)__cvta_generic_to_shared(Wbuf);

    // stage resident dup W1, dup biases, head weights
    for (int i = tx; i < 3328; i += THREADS) ((float2*)W1s)[i] = g_w1d[i];
    {
        float v;
        v = b1g[tx]; ((float2*)b1d)[tx] = make_float2(v, v);
        v = b2g[tx]; ((float2*)b2d)[tx] = make_float2(v, v);
        v = b3g[tx]; ((float2*)b3d)[tx] = make_float2(v, v);
    }
    for (int i = tx; i < 512; i += THREADS) wmuS[i] = wmu[i];
    if (tx < 2) bmuS[tx] = bmug[tx];

    // per-lane rollout state
    float px = 0.f, py = 0.f, wx = 0.f, wy = 0.f;
    float m_s = -1e30f, s_s = 0.f, m_r = -1e30f, s_r = 0.f;
    if (tx < TILE_B) {
        px = pos0[(b0 + tx) * 2 + 0]; py = pos0[(b0 + tx) * 2 + 1];
        wx = wind[(b0 + tx) * 2 + 0]; wy = wind[(b0 + tx) * 2 + 1];
        write_obs_T(obsT, tx, px, py);
    }
    __syncthreads();

    #pragma unroll 1
    for (int t = 0; t < 64; t++) {
        // start streaming layer-2 weights while layer 1 computes
        pf_tile(wbufs, g_w2d, 0, tx);
        pf_tile(wbufs + 32768u, g_w2d, 1, tx);

        layer_in(obsT, actA, W1s, b1d, tx);
        layer_mid(actA, actB, g_w2d, b2d, Wbuf, wbufs, tx, true);
        layer_mid(actB, actA, g_w3d, b3d, Wbuf, wbufs, tx, false);

        // output head: a = clip(h3 @ wmu + bmu); h3 is k-major in actA
        if (tx < 64) {
            int m = tx & 1, b = tx >> 1;
            float a0 = bmuS[m], a1 = 0.f, a2 = 0.f, a3 = 0.f;
            #pragma unroll 8
            for (int j = 0; j < 256; j += 4) {
                a0 = fmaf(actA[(j + 0) * 32 + b], wmuS[(j + 0) * 2 + m], a0);
                a1 = fmaf(actA[(j + 1) * 32 + b], wmuS[(j + 1) * 2 + m], a1);
                a2 = fmaf(actA[(j + 2) * 32 + b], wmuS[(j + 2) * 2 + m], a2);
                a3 = fmaf(actA[(j + 3) * 32 + b], wmuS[(j + 3) * 2 + m], a3);
            }
            float acc = (a0 + a1) + (a2 + a3);
            aS[b * 2 + m] = fminf(fmaxf(acc, -1.f), 1.f);
        }
        __syncthreads();

        // dynamics + online STREL accumulators + next obs
        if (tx < TILE_B) {
            float vx = 2.f * aS[tx * 2 + 0] + wx;
            float vy = 2.f * aS[tx * 2 + 1] + wy;
            #pragma unroll
            for (int s = 0; s < 4; s++) {
                px = fminf(fmaxf(px + 0.0625f * vx, -4.f), 10.f);
                py = fminf(fmaxf(py + 0.0625f * vy, -4.f), 10.f);
            }
            float dx = px - 1.75f, dy = py - 1.75f;
            float x0 = -50.f * (sqrtf(dx * dx + dy * dy + 1e-9f) - 0.38f);
            dx = px - 1.75f; dy = py - 3.75f;
            float x1 = -50.f * (sqrtf(dx * dx + dy * dy + 1e-9f) - 0.42f);
            dx = px - 3.75f; dy = py - 2.00f;
            float x2 = -50.f * (sqrtf(dx * dx + dy * dy + 1e-9f) - 0.34f);
            float mm = fmaxf(x0, fmaxf(x1, x2));
            float safe = -(mm + logf(expf(x0 - mm) + expf(x1 - mm) + expf(x2 - mm))) * 0.02f;

            float dgx = px - 4.f, dgy = py - 3.f;
            float reach = 0.45f - sqrtf(dgx * dgx + dgy * dgy + 1e-9f);

            float xs = -8.f * safe;
            if (xs > m_s) { s_s = s_s * expf(m_s - xs) + 1.f; m_s = xs; }
            else          { s_s += expf(xs - m_s); }
            float xr = 8.f * reach;
            if (xr > m_r) { s_r = s_r * expf(m_r - xr) + 1.f; m_r = xr; }
            else          { s_r += expf(xr - m_r); }

            write_obs_T(obsT, tx, px, py);
        }
        __syncthreads();
    }

    if (tx < TILE_B) {
        float rho_safe  = -(m_s + logf(s_s)) * 0.125f;
        float rho_reach =  (m_r + logf(s_r)) * 0.125f;
        float u0 = -8.f * rho_safe, u1 = -8.f * rho_reach;
        float mm = fmaxf(u0, u1);
        float rho = -(mm + logf(expf(u0 - mm) + expf(u1 - mm))) * 0.125f;
        out[b0 + tx] = rho;
    }
}

extern "C" void kernel_launch(void* const* d_in, const int* in_sizes, int n_in,
                              void* d_out, int out_size) {
    const float* pos0 = (const float*)d_in[0];
    const float* wind = (const float*)d_in[1];
    const float* w1   = (const float*)d_in[2];
    const float* b1   = (const float*)d_in[3];
    const float* w2   = (const float*)d_in[4];
    const float* b2   = (const float*)d_in[5];
    const float* w3   = (const float*)d_in[6];
    const float* b3   = (const float*)d_in[7];
    const float* wmu  = (const float*)d_in[8];
    const float* bmu  = (const float*)d_in[9];
    float* out = (float*)d_out;

    dup_weights_kernel<<<256, 256>>>(w1, w2, w3);

    cudaFuncSetAttribute(rollout_kernel,
                         cudaFuncAttributeMaxDynamicSharedMemorySize, SMEM_BYTES);
    int grid = out_size / TILE_B;  // 1024
    rollout_kernel<<<grid, THREADS, SMEM_BYTES>>>(pos0, wind, b1, b2, b3,
                                                  wmu, bmu, out);
}